// round 11
// baseline (speedup 1.0000x reference)
#include <cuda_runtime.h>
#include <cuda_fp16.h>
#include <math.h>
#include <stdint.h>

#define BB 2
#define SS 4096
#define HH 768
#define NHH 12
#define DHH 64
#define MM (BB * SS)
#define NBH (BB * NHH)

typedef unsigned long long u64;
typedef unsigned int u32;

// fp16 scratch
__device__ __half g_xh[(size_t)MM * HH];
__device__ __half g_wq[(size_t)HH * HH];
__device__ __half g_wk[(size_t)HH * HH];
__device__ __half g_wv[(size_t)HH * HH];
__device__ __half g_qh[(size_t)NBH * SS * DHH];   // Q pre-scaled by 0.125*log2(e)
__device__ __half g_kh[(size_t)NBH * SS * DHH];
__device__ __half g_vh[(size_t)NBH * SS * DHH];

__device__ __forceinline__ u32 smem_u32(const void* p) {
    u32 a; asm("{ .reg .u64 t; cvta.to.shared.u64 t, %1; cvt.u32.u64 %0, t; }" : "=r"(a) : "l"(p));
    return a;
}

// ---------------- mma.sync / ldmatrix / cp.async ----------------
#define LDSM4(r, a) \
    asm volatile("ldmatrix.sync.aligned.m8n8.x4.shared.b16 {%0,%1,%2,%3}, [%4];" \
        : "=r"((r)[0]), "=r"((r)[1]), "=r"((r)[2]), "=r"((r)[3]) : "r"(a))
#define LDSM4T(r, a) \
    asm volatile("ldmatrix.sync.aligned.m8n8.x4.trans.shared.b16 {%0,%1,%2,%3}, [%4];" \
        : "=r"((r)[0]), "=r"((r)[1]), "=r"((r)[2]), "=r"((r)[3]) : "r"(a))
// fp32-accumulator MMA
#define MMA(c, a, b0v, b1v) \
    asm volatile("mma.sync.aligned.m16n8k16.row.col.f32.f16.f16.f32 " \
        "{%0,%1,%2,%3}, {%4,%5,%6,%7}, {%8,%9}, {%0,%1,%2,%3};" \
        : "+f"((c)[0]), "+f"((c)[1]), "+f"((c)[2]), "+f"((c)[3]) \
        : "r"((a)[0]), "r"((a)[1]), "r"((a)[2]), "r"((a)[3]), "r"(b0v), "r"(b1v))
// fp16-accumulator MMA (QK path)
#define MMAH(c, a, b0v, b1v) \
    asm volatile("mma.sync.aligned.m16n8k16.row.col.f16.f16.f16.f16 " \
        "{%0,%1}, {%2,%3,%4,%5}, {%6,%7}, {%0,%1};" \
        : "+r"((c)[0]), "+r"((c)[1]) \
        : "r"((a)[0]), "r"((a)[1]), "r"((a)[2]), "r"((a)[3]), "r"(b0v), "r"(b1v))
__device__ __forceinline__ void cp16(u32 saddr, const void* g) {
    asm volatile("cp.async.cg.shared.global [%0], [%1], 16;" :: "r"(saddr), "l"(g));
}
#define CP_COMMIT() asm volatile("cp.async.commit_group;")
#define CP_WAIT0()  asm volatile("cp.async.wait_group 0;")
#define CP_WAIT1()  asm volatile("cp.async.wait_group 1;")
__device__ __forceinline__ u32 cvtpack(float lo, float hi) {
    u32 d; asm("cvt.rn.f16x2.f32 %0, %1, %2;" : "=r"(d) : "f"(hi), "f"(lo)); return d;
}
__device__ __forceinline__ u32 ex2h2(u32 x) {
    u32 r; asm("ex2.approx.f16x2 %0, %1;" : "=r"(r) : "r"(x)); return r;
}
__device__ __forceinline__ u32 haddp(u32 a, u32 b) {
    u32 r; asm("add.rn.f16x2 %0, %1, %2;" : "=r"(r) : "r"(a), "r"(b)); return r;
}

// ---------------------------------------------------------------------------
// fp32 -> fp16 converters
// ---------------------------------------------------------------------------
__global__ __launch_bounds__(192)
void half_rows_kernel(const float* __restrict__ src, __half* __restrict__ dst)
{
    const size_t o = (size_t)blockIdx.x * HH + threadIdx.x * 4;
    float4 v = *(const float4*)&src[o];
    *(uint2*)&dst[o] = make_uint2(cvtpack(v.x, v.y), cvtpack(v.z, v.w));
}

__global__ __launch_bounds__(192)
void half_w3_kernel(const float* __restrict__ wq_f, const float* __restrict__ wk_f,
                    const float* __restrict__ wv_f,
                    __half* __restrict__ wq_h, __half* __restrict__ wk_h,
                    __half* __restrict__ wv_h)
{
    const int z = blockIdx.y;
    const float* src = (z == 0) ? wq_f : (z == 1) ? wk_f : wv_f;
    __half* dst = (z == 0) ? wq_h : (z == 1) ? wk_h : wv_h;
    const size_t o = (size_t)blockIdx.x * HH + threadIdx.x * 4;
    float4 v = *(const float4*)&src[o];
    *(uint2*)&dst[o] = make_uint2(cvtpack(v.x, v.y), cvtpack(v.z, v.w));
}

// ---------------------------------------------------------------------------
// fp16 tensor-core GEMM + bias + head-layout fp16 epilogue. (unchanged)
// ---------------------------------------------------------------------------
#define XRS 144
#define WRS 272
#define GXT (128 * XRS)
#define GWT (64 * WRS)
#define GBUF (GXT + GWT)
#define GSM  (2 * GBUF)

__global__ __launch_bounds__(256, 1)
void gemm_tc_kernel(const __half* __restrict__ Xh,
                    const __half* __restrict__ Wq_h, const __half* __restrict__ Wk_h,
                    const __half* __restrict__ Wv_h,
                    const float* __restrict__ bq, const float* __restrict__ bk,
                    const float* __restrict__ bv,
                    __half* __restrict__ qo, __half* __restrict__ ko,
                    __half* __restrict__ vo)
{
    const int z = blockIdx.z;
    const __half* Wh = (z == 0) ? Wq_h : (z == 1) ? Wk_h : Wv_h;
    const float* bias = (z == 0) ? bq : (z == 1) ? bk : bv;
    __half* gout = (z == 0) ? qo : (z == 1) ? ko : vo;
    const float scale = (z == 0) ? 0.18033688011112042f : 1.0f;

    extern __shared__ char smem[];
    const u32 sb = smem_u32(smem);
    const int tid = threadIdx.x;
    const int w = tid >> 5, lane = tid & 31;
    const int wm = w >> 1, wn = w & 1;
    const int bn = blockIdx.x * 128;
    const int bm = blockIdx.y * 128;

    float acc[2][8][4];
    #pragma unroll
    for (int mi = 0; mi < 2; mi++)
        #pragma unroll
        for (int j = 0; j < 8; j++)
            #pragma unroll
            for (int i = 0; i < 4; i++) acc[mi][j][i] = 0.0f;

    const int frow = (lane & 7) + ((lane >> 3) & 1) * 8;
    const u32 aoff = (u32)(frow * XRS + (lane >> 4) * 16);
    const u32 boff = (u32)(frow * WRS + (lane >> 4) * 16);

    {
        const u32 buf = sb;
        #pragma unroll
        for (int i = 0; i < 4; i++) {
            int c = tid + i * 256;
            int r = c >> 3, o = c & 7;
            cp16(buf + (u32)(r * XRS + o * 16), Xh + (size_t)(bm + r) * HH + o * 8);
        }
        #pragma unroll
        for (int i = 0; i < 4; i++) {
            int c = tid + i * 256;
            int r = c >> 4, o = c & 15;
            cp16(buf + GXT + (u32)(r * WRS + o * 16), Wh + (size_t)r * HH + bn + o * 8);
        }
        CP_COMMIT();
    }

    for (int kc = 0; kc < 12; kc++) {
        if (kc < 11) {
            const u32 buf = sb + ((kc + 1) & 1) * GBUF;
            const int kb = (kc + 1) * 64;
            #pragma unroll
            for (int i = 0; i < 4; i++) {
                int c = tid + i * 256;
                int r = c >> 3, o = c & 7;
                cp16(buf + (u32)(r * XRS + o * 16), Xh + (size_t)(bm + r) * HH + kb + o * 8);
            }
            #pragma unroll
            for (int i = 0; i < 4; i++) {
                int c = tid + i * 256;
                int r = c >> 4, o = c & 15;
                cp16(buf + GXT + (u32)(r * WRS + o * 16), Wh + (size_t)(kb + r) * HH + bn + o * 8);
            }
            CP_COMMIT();
            CP_WAIT1();
        } else {
            CP_WAIT0();
        }
        __syncthreads();

        const u32 XT = sb + (kc & 1) * GBUF;
        const u32 WT = XT + GXT;

        #pragma unroll
        for (int kk = 0; kk < 4; kk++) {
            u32 ah[2][4];
            #pragma unroll
            for (int mi = 0; mi < 2; mi++) {
                u32 a = (u32)((wm * 32 + mi * 16) * XRS) + aoff + kk * 32;
                LDSM4(ah[mi], XT + a);
            }
            #pragma unroll
            for (int nt = 0; nt < 4; nt++) {
                u32 bo = (u32)(kk * 16 * WRS) + boff + (u32)(wn * 128 + nt * 32);
                u32 bh[4];
                LDSM4T(bh, WT + bo);
                #pragma unroll
                for (int mi = 0; mi < 2; mi++) {
                    MMA(acc[mi][2 * nt],     ah[mi], bh[0], bh[1]);
                    MMA(acc[mi][2 * nt + 1], ah[mi], bh[2], bh[3]);
                }
            }
        }
        __syncthreads();
    }

    const int h  = (bn >> 6) + wn;
    const int cl = (lane & 3) * 2;
    const int rl = lane >> 2;
    #pragma unroll
    for (int j = 0; j < 8; j++) {
        const int d = j * 8 + cl;
        const float bx = bias[bn + wn * 64 + d];
        const float by = bias[bn + wn * 64 + d + 1];
        #pragma unroll
        for (int mi = 0; mi < 2; mi++) {
            #pragma unroll
            for (int rr = 0; rr < 2; rr++) {
                const int m = bm + wm * 32 + mi * 16 + rl + rr * 8;
                const int b = m >> 12, s = m & 4095;
                const size_t o = ((size_t)(b * NHH + h) * SS + s) * DHH + d;
                const float y0 = (acc[mi][j][2 * rr]     + bx) * scale;
                const float y1 = (acc[mi][j][2 * rr + 1] + by) * scale;
                *(u32*)&gout[o] = cvtpack(y0, y1);
            }
        }
    }
}

// ---------------------------------------------------------------------------
// mma.sync flash attention v4: 4 warps x 16 q-rows (64-row CTA), 3 CTAs/SM.
// QK fp16-acc -> ex2.f16x2 -> packed P; PV fp32-acc.
// ---------------------------------------------------------------------------
#define RS 144
#define ARR_BYTES (128 * RS)
#define BUF_BYTES (2 * ARR_BYTES)
#define SM_TOTAL  (2 * BUF_BYTES)     // 73728

__global__ __launch_bounds__(128, 3)
void attn_mma_kernel(const __half* __restrict__ qh_g,
                     const __half* __restrict__ kh_g,
                     const __half* __restrict__ vh_g,
                     float* __restrict__ out)
{
    extern __shared__ char smem[];
    const u32 sb = smem_u32(smem);
    const int tid  = threadIdx.x;
    const int w    = tid >> 5;
    const int lane = tid & 31;
    const int qt = blockIdx.x;            // 64-row q tile, 0..63
    const int bh = blockIdx.y;
    const int b = bh / NHH, h = bh % NHH;

    const size_t bh_base = (size_t)bh * SS * DHH;

    // ---- stage Q (64 rows) into buffer 1, extract A-fragments, reclaim ----
    {
        const u32 QB = sb + BUF_BYTES;
        const __half* qg = qh_g + bh_base + (size_t)qt * 64 * DHH;
        #pragma unroll
        for (int i = 0; i < 4; i++) {
            int c = tid + i * 128;
            int r = c >> 3, o = c & 7;
            cp16(QB + (u32)(r * RS + o * 16), qg + (size_t)r * DHH + o * 8);
        }
        CP_COMMIT();
        CP_WAIT0();
        __syncthreads();
    }

    const int frow = (lane & 7) + ((lane >> 3) & 1) * 8;
    u32 qf[4][4];
    {
        const u32 QB = sb + BUF_BYTES;
        u32 rbase = (u32)((w * 16 + frow) * RS + (lane >> 4) * 16);
        #pragma unroll
        for (int k = 0; k < 4; k++)
            LDSM4(qf[k], QB + rbase + k * 32);
    }
    __syncthreads();

    float ctx[8][4];
    #pragma unroll
    for (int n = 0; n < 8; n++)
        #pragma unroll
        for (int i = 0; i < 4; i++) ctx[n][i] = 0.0f;
    float ls0 = 0.0f, ls1 = 0.0f;

    const u32 koff = (u32)(((lane >> 4) * 8 + (lane & 7)) * RS + ((lane >> 3) & 1) * 16);
    const u32 voff = (u32)((((lane >> 3) & 1) * 8 + (lane & 7)) * RS + (lane >> 4) * 16);

    // tile 0 -> buffer 0
    {
        #pragma unroll
        for (int i = 0; i < 8; i++) {
            int c = tid + i * 128;
            int r = c >> 3, o = c & 7;
            u32 so = (u32)(r * RS + o * 16);
            cp16(sb + so,             kh_g + bh_base + (size_t)r * DHH + o * 8);
            cp16(sb + ARR_BYTES + so, vh_g + bh_base + (size_t)r * DHH + o * 8);
        }
        CP_COMMIT();
    }

    for (int t = 0; t < 32; ++t) {
        if (t < 31) {
            const u32 nb = sb + ((t + 1) & 1) * BUF_BYTES;
            const size_t gb = bh_base + (size_t)(t + 1) * 128 * DHH;
            #pragma unroll
            for (int i = 0; i < 8; i++) {
                int c = tid + i * 128;
                int r = c >> 3, o = c & 7;
                u32 so = (u32)(r * RS + o * 16);
                cp16(nb + so,             kh_g + gb + (size_t)r * DHH + o * 8);
                cp16(nb + ARR_BYTES + so, vh_g + gb + (size_t)r * DHH + o * 8);
            }
            CP_COMMIT();
            CP_WAIT1();
        } else {
            CP_WAIT0();
        }
        __syncthreads();

        const u32 KH = sb + (t & 1) * BUF_BYTES;
        const u32 VS = KH + ARR_BYTES;

        // per-tile packed fp16 row-sum accumulators
        u32 hls0 = 0u, hls1 = 0u;

        #pragma unroll
        for (int j = 0; j < 8; j++) {
            const u32 bj = (u32)(j * 16 * RS);

            u32 khf[4][4];
            #pragma unroll
            for (int k = 0; k < 4; k++)
                LDSM4(khf[k], KH + bj + koff + k * 32);

            u32 sA[2] = {0u, 0u};
            u32 sB[2] = {0u, 0u};
            #pragma unroll
            for (int k = 0; k < 4; k++) {
                MMAH(sA, qf[k], khf[k][0], khf[k][1]);
                MMAH(sB, qf[k], khf[k][2], khf[k][3]);
            }

            u32 vf[4][4];
            #pragma unroll
            for (int tt = 0; tt < 4; tt++)
                LDSM4T(vf[tt], VS + bj + voff + tt * 32);

            u32 pa[4];
            pa[0] = ex2h2(sA[0]);
            pa[1] = ex2h2(sA[1]);
            pa[2] = ex2h2(sB[0]);
            pa[3] = ex2h2(sB[1]);
            hls0 = haddp(hls0, haddp(pa[0], pa[2]));
            hls1 = haddp(hls1, haddp(pa[1], pa[3]));

            #pragma unroll
            for (int tt = 0; tt < 4; tt++) {
                MMA(ctx[2 * tt],     pa, vf[tt][0], vf[tt][1]);
                MMA(ctx[2 * tt + 1], pa, vf[tt][2], vf[tt][3]);
            }
        }

        // fold per-tile fp16 row-sums into fp32
        {
            float2 f0 = __half22float2(*(__half2*)&hls0);
            float2 f1 = __half22float2(*(__half2*)&hls1);
            ls0 += f0.x + f0.y;
            ls1 += f1.x + f1.y;
        }
        __syncthreads();
    }

    {
        float l0 = ls0, l1 = ls1;
        l0 += __shfl_xor_sync(0xffffffffu, l0, 1);
        l0 += __shfl_xor_sync(0xffffffffu, l0, 2);
        l1 += __shfl_xor_sync(0xffffffffu, l1, 1);
        l1 += __shfl_xor_sync(0xffffffffu, l1, 2);
        const float inv0 = 1.0f / l0;
        const float inv1 = 1.0f / l1;

        const int row0 = qt * 64 + w * 16 + (lane >> 2);
        const int colb = 2 * (lane & 3);
        float* o0 = out + ((size_t)(b * SS) + row0) * HH + h * DHH + colb;
        float* o1 = o0 + 8 * HH;
        #pragma unroll
        for (int n = 0; n < 8; n++) {
            float2 r0, r1;
            r0.x = tanhf(ctx[n][0] * inv0);
            r0.y = tanhf(ctx[n][1] * inv0);
            r1.x = tanhf(ctx[n][2] * inv1);
            r1.y = tanhf(ctx[n][3] * inv1);
            *(float2*)(o0 + 8 * n) = r0;
            *(float2*)(o1 + 8 * n) = r1;
        }
    }
}

// ---------------------------------------------------------------------------
extern "C" void kernel_launch(void* const* d_in, const int* in_sizes, int n_in,
                              void* d_out, int out_size)
{
    const float* x  = (const float*)d_in[0];
    const float* Wq = (const float*)d_in[1];
    const float* bq = (const float*)d_in[2];
    const float* Wk = (const float*)d_in[3];
    const float* bk = (const float*)d_in[4];
    const float* Wv = (const float*)d_in[5];
    const float* bv = (const float*)d_in[6];
    float* out = (float*)d_out;

    __half *xh, *wq, *wk, *wv, *qh, *kh, *vh;
    cudaGetSymbolAddress((void**)&xh, g_xh);
    cudaGetSymbolAddress((void**)&wq, g_wq);
    cudaGetSymbolAddress((void**)&wk, g_wk);
    cudaGetSymbolAddress((void**)&wv, g_wv);
    cudaGetSymbolAddress((void**)&qh, g_qh);
    cudaGetSymbolAddress((void**)&kh, g_kh);
    cudaGetSymbolAddress((void**)&vh, g_vh);

    cudaFuncSetAttribute(gemm_tc_kernel, cudaFuncAttributeMaxDynamicSharedMemorySize, GSM);
    cudaFuncSetAttribute(attn_mma_kernel, cudaFuncAttributeMaxDynamicSharedMemorySize, SM_TOTAL);

    half_rows_kernel<<<MM, 192>>>(x, xh);
    half_w3_kernel<<<dim3(HH, 3), 192>>>(Wq, Wk, Wv, wq, wk, wv);

    dim3 ggrid(HH / 128, MM / 128, 3);
    gemm_tc_kernel<<<ggrid, 256, GSM>>>(xh, wq, wk, wv, bq, bk, bv, qh, kh, vh);

    dim3 agrid(SS / 64, NBH);   // 64-row q tiles
    attn_mma_kernel<<<agrid, 128, SM_TOTAL>>>(qh, kh, vh, out);
}

// round 12
// speedup vs baseline: 1.0547x; 1.0547x over previous
#include <cuda_runtime.h>
#include <cuda_fp16.h>
#include <math.h>
#include <stdint.h>

#define BB 2
#define SS 4096
#define HH 768
#define NHH 12
#define DHH 64
#define MM (BB * SS)
#define NBH (BB * NHH)

typedef unsigned long long u64;
typedef unsigned int u32;

// fp16 scratch
__device__ __half g_xh[(size_t)MM * HH];
__device__ __half g_wq[(size_t)HH * HH];
__device__ __half g_wk[(size_t)HH * HH];
__device__ __half g_wv[(size_t)HH * HH];
__device__ __half g_qh[(size_t)NBH * SS * DHH];   // Q pre-scaled by 0.125*log2(e)
__device__ __half g_kh[(size_t)NBH * SS * DHH];
__device__ __half g_vh[(size_t)NBH * SS * DHH];

__device__ __forceinline__ u32 smem_u32(const void* p) {
    u32 a; asm("{ .reg .u64 t; cvta.to.shared.u64 t, %1; cvt.u32.u64 %0, t; }" : "=r"(a) : "l"(p));
    return a;
}

// ---------------- mma.sync / ldmatrix / cp.async ----------------
#define LDSM4(r, a) \
    asm volatile("ldmatrix.sync.aligned.m8n8.x4.shared.b16 {%0,%1,%2,%3}, [%4];" \
        : "=r"((r)[0]), "=r"((r)[1]), "=r"((r)[2]), "=r"((r)[3]) : "r"(a))
#define LDSM4T(r, a) \
    asm volatile("ldmatrix.sync.aligned.m8n8.x4.trans.shared.b16 {%0,%1,%2,%3}, [%4];" \
        : "=r"((r)[0]), "=r"((r)[1]), "=r"((r)[2]), "=r"((r)[3]) : "r"(a))
// fp32-accumulator MMA
#define MMA(c, a, b0v, b1v) \
    asm volatile("mma.sync.aligned.m16n8k16.row.col.f32.f16.f16.f32 " \
        "{%0,%1,%2,%3}, {%4,%5,%6,%7}, {%8,%9}, {%0,%1,%2,%3};" \
        : "+f"((c)[0]), "+f"((c)[1]), "+f"((c)[2]), "+f"((c)[3]) \
        : "r"((a)[0]), "r"((a)[1]), "r"((a)[2]), "r"((a)[3]), "r"(b0v), "r"(b1v))
// fp16-accumulator MMA (QK path)
#define MMAH(c, a, b0v, b1v) \
    asm volatile("mma.sync.aligned.m16n8k16.row.col.f16.f16.f16.f16 " \
        "{%0,%1}, {%2,%3,%4,%5}, {%6,%7}, {%0,%1};" \
        : "+r"((c)[0]), "+r"((c)[1]) \
        : "r"((a)[0]), "r"((a)[1]), "r"((a)[2]), "r"((a)[3]), "r"(b0v), "r"(b1v))
__device__ __forceinline__ void cp16(u32 saddr, const void* g) {
    asm volatile("cp.async.cg.shared.global [%0], [%1], 16;" :: "r"(saddr), "l"(g));
}
#define CP_COMMIT() asm volatile("cp.async.commit_group;")
#define CP_WAIT0()  asm volatile("cp.async.wait_group 0;")
#define CP_WAIT1()  asm volatile("cp.async.wait_group 1;")
__device__ __forceinline__ u32 cvtpack(float lo, float hi) {
    u32 d; asm("cvt.rn.f16x2.f32 %0, %1, %2;" : "=r"(d) : "f"(hi), "f"(lo)); return d;
}
__device__ __forceinline__ u32 ex2h2(u32 x) {
    u32 r; asm("ex2.approx.f16x2 %0, %1;" : "=r"(r) : "r"(x)); return r;
}
__device__ __forceinline__ u32 haddp(u32 a, u32 b) {
    u32 r; asm("add.rn.f16x2 %0, %1, %2;" : "=r"(r) : "r"(a), "r"(b)); return r;
}

// ---------------------------------------------------------------------------
// fp32 -> fp16 converters
// ---------------------------------------------------------------------------
__global__ __launch_bounds__(192)
void half_rows_kernel(const float* __restrict__ src, __half* __restrict__ dst)
{
    const size_t o = (size_t)blockIdx.x * HH + threadIdx.x * 4;
    float4 v = *(const float4*)&src[o];
    *(uint2*)&dst[o] = make_uint2(cvtpack(v.x, v.y), cvtpack(v.z, v.w));
}

__global__ __launch_bounds__(192)
void half_w3_kernel(const float* __restrict__ wq_f, const float* __restrict__ wk_f,
                    const float* __restrict__ wv_f,
                    __half* __restrict__ wq_h, __half* __restrict__ wk_h,
                    __half* __restrict__ wv_h)
{
    const int z = blockIdx.y;
    const float* src = (z == 0) ? wq_f : (z == 1) ? wk_f : wv_f;
    __half* dst = (z == 0) ? wq_h : (z == 1) ? wk_h : wv_h;
    const size_t o = (size_t)blockIdx.x * HH + threadIdx.x * 4;
    float4 v = *(const float4*)&src[o];
    *(uint2*)&dst[o] = make_uint2(cvtpack(v.x, v.y), cvtpack(v.z, v.w));
}

// ---------------------------------------------------------------------------
// fp16 tensor-core GEMM + bias + head-layout fp16 epilogue. (unchanged)
// ---------------------------------------------------------------------------
#define XRS 144
#define WRS 272
#define GXT (128 * XRS)
#define GWT (64 * WRS)
#define GBUF (GXT + GWT)
#define GSM  (2 * GBUF)

__global__ __launch_bounds__(256, 1)
void gemm_tc_kernel(const __half* __restrict__ Xh,
                    const __half* __restrict__ Wq_h, const __half* __restrict__ Wk_h,
                    const __half* __restrict__ Wv_h,
                    const float* __restrict__ bq, const float* __restrict__ bk,
                    const float* __restrict__ bv,
                    __half* __restrict__ qo, __half* __restrict__ ko,
                    __half* __restrict__ vo)
{
    const int z = blockIdx.z;
    const __half* Wh = (z == 0) ? Wq_h : (z == 1) ? Wk_h : Wv_h;
    const float* bias = (z == 0) ? bq : (z == 1) ? bk : bv;
    __half* gout = (z == 0) ? qo : (z == 1) ? ko : vo;
    const float scale = (z == 0) ? 0.18033688011112042f : 1.0f;

    extern __shared__ char smem[];
    const u32 sb = smem_u32(smem);
    const int tid = threadIdx.x;
    const int w = tid >> 5, lane = tid & 31;
    const int wm = w >> 1, wn = w & 1;
    const int bn = blockIdx.x * 128;
    const int bm = blockIdx.y * 128;

    float acc[2][8][4];
    #pragma unroll
    for (int mi = 0; mi < 2; mi++)
        #pragma unroll
        for (int j = 0; j < 8; j++)
            #pragma unroll
            for (int i = 0; i < 4; i++) acc[mi][j][i] = 0.0f;

    const int frow = (lane & 7) + ((lane >> 3) & 1) * 8;
    const u32 aoff = (u32)(frow * XRS + (lane >> 4) * 16);
    const u32 boff = (u32)(frow * WRS + (lane >> 4) * 16);

    {
        const u32 buf = sb;
        #pragma unroll
        for (int i = 0; i < 4; i++) {
            int c = tid + i * 256;
            int r = c >> 3, o = c & 7;
            cp16(buf + (u32)(r * XRS + o * 16), Xh + (size_t)(bm + r) * HH + o * 8);
        }
        #pragma unroll
        for (int i = 0; i < 4; i++) {
            int c = tid + i * 256;
            int r = c >> 4, o = c & 15;
            cp16(buf + GXT + (u32)(r * WRS + o * 16), Wh + (size_t)r * HH + bn + o * 8);
        }
        CP_COMMIT();
    }

    for (int kc = 0; kc < 12; kc++) {
        if (kc < 11) {
            const u32 buf = sb + ((kc + 1) & 1) * GBUF;
            const int kb = (kc + 1) * 64;
            #pragma unroll
            for (int i = 0; i < 4; i++) {
                int c = tid + i * 256;
                int r = c >> 3, o = c & 7;
                cp16(buf + (u32)(r * XRS + o * 16), Xh + (size_t)(bm + r) * HH + kb + o * 8);
            }
            #pragma unroll
            for (int i = 0; i < 4; i++) {
                int c = tid + i * 256;
                int r = c >> 4, o = c & 15;
                cp16(buf + GXT + (u32)(r * WRS + o * 16), Wh + (size_t)(kb + r) * HH + bn + o * 8);
            }
            CP_COMMIT();
            CP_WAIT1();
        } else {
            CP_WAIT0();
        }
        __syncthreads();

        const u32 XT = sb + (kc & 1) * GBUF;
        const u32 WT = XT + GXT;

        #pragma unroll
        for (int kk = 0; kk < 4; kk++) {
            u32 ah[2][4];
            #pragma unroll
            for (int mi = 0; mi < 2; mi++) {
                u32 a = (u32)((wm * 32 + mi * 16) * XRS) + aoff + kk * 32;
                LDSM4(ah[mi], XT + a);
            }
            #pragma unroll
            for (int nt = 0; nt < 4; nt++) {
                u32 bo = (u32)(kk * 16 * WRS) + boff + (u32)(wn * 128 + nt * 32);
                u32 bh[4];
                LDSM4T(bh, WT + bo);
                #pragma unroll
                for (int mi = 0; mi < 2; mi++) {
                    MMA(acc[mi][2 * nt],     ah[mi], bh[0], bh[1]);
                    MMA(acc[mi][2 * nt + 1], ah[mi], bh[2], bh[3]);
                }
            }
        }
        __syncthreads();
    }

    const int h  = (bn >> 6) + wn;
    const int cl = (lane & 3) * 2;
    const int rl = lane >> 2;
    #pragma unroll
    for (int j = 0; j < 8; j++) {
        const int d = j * 8 + cl;
        const float bx = bias[bn + wn * 64 + d];
        const float by = bias[bn + wn * 64 + d + 1];
        #pragma unroll
        for (int mi = 0; mi < 2; mi++) {
            #pragma unroll
            for (int rr = 0; rr < 2; rr++) {
                const int m = bm + wm * 32 + mi * 16 + rl + rr * 8;
                const int b = m >> 12, s = m & 4095;
                const size_t o = ((size_t)(b * NHH + h) * SS + s) * DHH + d;
                const float y0 = (acc[mi][j][2 * rr]     + bx) * scale;
                const float y1 = (acc[mi][j][2 * rr + 1] + by) * scale;
                *(u32*)&gout[o] = cvtpack(y0, y1);
            }
        }
    }
}

// ---------------------------------------------------------------------------
// mma.sync flash attention v5: R10 shape (4 warps x 32 q-rows, 2 CTAs/SM),
// software-pipelined (j,mi) stages: next stage's QK MMAs issued in the
// ex2 shadow of the current stage.
// ---------------------------------------------------------------------------
#define RS 144
#define ARR_BYTES (128 * RS)
#define BUF_BYTES (2 * ARR_BYTES)
#define SM_TOTAL  (2 * BUF_BYTES)     // 73728

__global__ __launch_bounds__(128, 2)
void attn_mma_kernel(const __half* __restrict__ qh_g,
                     const __half* __restrict__ kh_g,
                     const __half* __restrict__ vh_g,
                     float* __restrict__ out)
{
    extern __shared__ char smem[];
    const u32 sb = smem_u32(smem);
    const int tid  = threadIdx.x;
    const int w    = tid >> 5;
    const int lane = tid & 31;
    const int qt = blockIdx.x;
    const int bh = blockIdx.y;
    const int b = bh / NHH, h = bh % NHH;

    const size_t bh_base = (size_t)bh * SS * DHH;

    // ---- stage Q (128 rows) into buffer 1, extract 2 A-fragments/warp ----
    {
        const u32 QB = sb + BUF_BYTES;
        const __half* qg = qh_g + bh_base + (size_t)qt * 128 * DHH;
        #pragma unroll
        for (int i = 0; i < 8; i++) {
            int c = tid + i * 128;
            int r = c >> 3, o = c & 7;
            cp16(QB + (u32)(r * RS + o * 16), qg + (size_t)r * DHH + o * 8);
        }
        CP_COMMIT();
        CP_WAIT0();
        __syncthreads();
    }

    const int frow = (lane & 7) + ((lane >> 3) & 1) * 8;
    u32 qf[2][4][4];
    {
        const u32 QB = sb + BUF_BYTES;
        #pragma unroll
        for (int mi = 0; mi < 2; mi++) {
            u32 rbase = (u32)((w * 32 + mi * 16 + frow) * RS + (lane >> 4) * 16);
            #pragma unroll
            for (int k = 0; k < 4; k++)
                LDSM4(qf[mi][k], QB + rbase + k * 32);
        }
    }
    __syncthreads();

    float ctx[2][8][4];
    #pragma unroll
    for (int mi = 0; mi < 2; mi++)
        #pragma unroll
        for (int n = 0; n < 8; n++)
            #pragma unroll
            for (int i = 0; i < 4; i++) ctx[mi][n][i] = 0.0f;
    float ls[2][2] = {{0.f, 0.f}, {0.f, 0.f}};

    const u32 koff = (u32)(((lane >> 4) * 8 + (lane & 7)) * RS + ((lane >> 3) & 1) * 16);
    const u32 voff = (u32)((((lane >> 3) & 1) * 8 + (lane & 7)) * RS + (lane >> 4) * 16);

    // tile 0 -> buffer 0
    {
        #pragma unroll
        for (int i = 0; i < 8; i++) {
            int c = tid + i * 128;
            int r = c >> 3, o = c & 7;
            u32 so = (u32)(r * RS + o * 16);
            cp16(sb + so,             kh_g + bh_base + (size_t)r * DHH + o * 8);
            cp16(sb + ARR_BYTES + so, vh_g + bh_base + (size_t)r * DHH + o * 8);
        }
        CP_COMMIT();
    }

    for (int t = 0; t < 32; ++t) {
        if (t < 31) {
            const u32 nb = sb + ((t + 1) & 1) * BUF_BYTES;
            const size_t gb = bh_base + (size_t)(t + 1) * 128 * DHH;
            #pragma unroll
            for (int i = 0; i < 8; i++) {
                int c = tid + i * 128;
                int r = c >> 3, o = c & 7;
                u32 so = (u32)(r * RS + o * 16);
                cp16(nb + so,             kh_g + gb + (size_t)r * DHH + o * 8);
                cp16(nb + ARR_BYTES + so, vh_g + gb + (size_t)r * DHH + o * 8);
            }
            CP_COMMIT();
            CP_WAIT1();
        } else {
            CP_WAIT0();
        }
        __syncthreads();

        const u32 KH = sb + (t & 1) * BUF_BYTES;
        const u32 VS = KH + ARR_BYTES;

        // per-tile packed fp16 row-sum accumulators [mi][row-group]
        u32 hls[2][2] = {{0u, 0u}, {0u, 0u}};

        // ---- tile prologue: khf(j=0), s for stage 0 (j=0, mi=0) ----
        u32 khf[4][4];
        #pragma unroll
        for (int k = 0; k < 4; k++)
            LDSM4(khf[k], KH + koff + k * 32);

        u32 scur[4] = {0u, 0u, 0u, 0u};
        #pragma unroll
        for (int k = 0; k < 4; k++) {
            MMAH(&scur[0], qf[0][k], khf[k][0], khf[k][1]);
            MMAH(&scur[2], qf[0][k], khf[k][2], khf[k][3]);
        }

        u32 vf[4][4];

        // ---- 16 pipelined stages: stage st = (j = st>>1, mi = st&1) ----
        #pragma unroll
        for (int st = 0; st < 16; st++) {
            const int j  = st >> 1;
            const int mi = st & 1;

            if (mi == 0) {
                const u32 bj = (u32)(j * 16 * RS);
                #pragma unroll
                for (int tt = 0; tt < 4; tt++)
                    LDSM4T(vf[tt], VS + bj + voff + tt * 32);
            }

            // p = exp2(s) — MUFU; its shadow is filled by next-stage QK below
            u32 pa[4];
            pa[0] = ex2h2(scur[0]);
            pa[1] = ex2h2(scur[1]);
            pa[2] = ex2h2(scur[2]);
            pa[3] = ex2h2(scur[3]);

            // issue next stage's QK MMAs (independent of pa)
            u32 snext[4] = {0u, 0u, 0u, 0u};
            if (st < 15) {
                const int mi2 = (st + 1) & 1;
                if (mi2 == 0) {
                    const int j2 = (st + 1) >> 1;
                    const u32 bj2 = (u32)(j2 * 16 * RS);
                    #pragma unroll
                    for (int k = 0; k < 4; k++)
                        LDSM4(khf[k], KH + bj2 + koff + k * 32);
                }
                #pragma unroll
                for (int k = 0; k < 4; k++) {
                    MMAH(&snext[0], qf[mi2][k], khf[k][0], khf[k][1]);
                    MMAH(&snext[2], qf[mi2][k], khf[k][2], khf[k][3]);
                }
            }

            // row sums + PV for current stage
            hls[mi][0] = haddp(hls[mi][0], haddp(pa[0], pa[2]));
            hls[mi][1] = haddp(hls[mi][1], haddp(pa[1], pa[3]));

            #pragma unroll
            for (int tt = 0; tt < 4; tt++) {
                MMA(ctx[mi][2 * tt],     pa, vf[tt][0], vf[tt][1]);
                MMA(ctx[mi][2 * tt + 1], pa, vf[tt][2], vf[tt][3]);
            }

            #pragma unroll
            for (int i = 0; i < 4; i++) scur[i] = snext[i];
        }

        // fold per-tile fp16 row-sums into fp32
        #pragma unroll
        for (int mi = 0; mi < 2; mi++) {
            float2 f0 = __half22float2(*(__half2*)&hls[mi][0]);
            float2 f1 = __half22float2(*(__half2*)&hls[mi][1]);
            ls[mi][0] += f0.x + f0.y;
            ls[mi][1] += f1.x + f1.y;
        }
        __syncthreads();
    }

    #pragma unroll
    for (int mi = 0; mi < 2; mi++) {
        float l0 = ls[mi][0], l1 = ls[mi][1];
        l0 += __shfl_xor_sync(0xffffffffu, l0, 1);
        l0 += __shfl_xor_sync(0xffffffffu, l0, 2);
        l1 += __shfl_xor_sync(0xffffffffu, l1, 1);
        l1 += __shfl_xor_sync(0xffffffffu, l1, 2);
        const float inv0 = 1.0f / l0;
        const float inv1 = 1.0f / l1;

        const int row0 = qt * 128 + w * 32 + mi * 16 + (lane >> 2);
        const int colb = 2 * (lane & 3);
        float* o0 = out + ((size_t)(b * SS) + row0) * HH + h * DHH + colb;
        float* o1 = o0 + 8 * HH;
        #pragma unroll
        for (int n = 0; n < 8; n++) {
            float2 r0, r1;
            r0.x = tanhf(ctx[mi][n][0] * inv0);
            r0.y = tanhf(ctx[mi][n][1] * inv0);
            r1.x = tanhf(ctx[mi][n][2] * inv1);
            r1.y = tanhf(ctx[mi][n][3] * inv1);
            *(float2*)(o0 + 8 * n) = r0;
            *(float2*)(o1 + 8 * n) = r1;
        }
    }
}

// ---------------------------------------------------------------------------
extern "C" void kernel_launch(void* const* d_in, const int* in_sizes, int n_in,
                              void* d_out, int out_size)
{
    const float* x  = (const float*)d_in[0];
    const float* Wq = (const float*)d_in[1];
    const float* bq = (const float*)d_in[2];
    const float* Wk = (const float*)d_in[3];
    const float* bk = (const float*)d_in[4];
    const float* Wv = (const float*)d_in[5];
    const float* bv = (const float*)d_in[6];
    float* out = (float*)d_out;

    __half *xh, *wq, *wk, *wv, *qh, *kh, *vh;
    cudaGetSymbolAddress((void**)&xh, g_xh);
    cudaGetSymbolAddress((void**)&wq, g_wq);
    cudaGetSymbolAddress((void**)&wk, g_wk);
    cudaGetSymbolAddress((void**)&wv, g_wv);
    cudaGetSymbolAddress((void**)&qh, g_qh);
    cudaGetSymbolAddress((void**)&kh, g_kh);
    cudaGetSymbolAddress((void**)&vh, g_vh);

    cudaFuncSetAttribute(gemm_tc_kernel, cudaFuncAttributeMaxDynamicSharedMemorySize, GSM);
    cudaFuncSetAttribute(attn_mma_kernel, cudaFuncAttributeMaxDynamicSharedMemorySize, SM_TOTAL);

    half_rows_kernel<<<MM, 192>>>(x, xh);
    half_w3_kernel<<<dim3(HH, 3), 192>>>(Wq, Wk, Wv, wq, wk, wv);

    dim3 ggrid(HH / 128, MM / 128, 3);
    gemm_tc_kernel<<<ggrid, 256, GSM>>>(xh, wq, wk, wv, bq, bk, bv, qh, kh, vh);

    dim3 agrid(SS / 128, NBH);   // back to 128-row q tiles (R10 shape)
    attn_mma_kernel<<<agrid, 128, SM_TOTAL>>>(qh, kh, vh, out);
}

// round 13
// speedup vs baseline: 1.1260x; 1.0676x over previous
#include <cuda_runtime.h>
#include <cuda_fp16.h>
#include <math.h>
#include <stdint.h>

#define BB 2
#define SS 4096
#define HH 768
#define NHH 12
#define DHH 64
#define MM (BB * SS)
#define NBH (BB * NHH)

typedef unsigned long long u64;
typedef unsigned int u32;

// fp16 scratch
__device__ __half g_xh[(size_t)MM * HH];
__device__ __half g_wq[(size_t)HH * HH];
__device__ __half g_wk[(size_t)HH * HH];
__device__ __half g_wv[(size_t)HH * HH];
__device__ __half g_qh[(size_t)NBH * SS * DHH];   // Q pre-scaled by 0.125*log2(e)
__device__ __half g_kh[(size_t)NBH * SS * DHH];
__device__ __half g_vh[(size_t)NBH * SS * DHH];

__device__ __forceinline__ u32 smem_u32(const void* p) {
    u32 a; asm("{ .reg .u64 t; cvta.to.shared.u64 t, %1; cvt.u32.u64 %0, t; }" : "=r"(a) : "l"(p));
    return a;
}

// ---------------- mma.sync / ldmatrix / cp.async ----------------
#define LDSM4(r, a) \
    asm volatile("ldmatrix.sync.aligned.m8n8.x4.shared.b16 {%0,%1,%2,%3}, [%4];" \
        : "=r"((r)[0]), "=r"((r)[1]), "=r"((r)[2]), "=r"((r)[3]) : "r"(a))
#define LDSM4T(r, a) \
    asm volatile("ldmatrix.sync.aligned.m8n8.x4.trans.shared.b16 {%0,%1,%2,%3}, [%4];" \
        : "=r"((r)[0]), "=r"((r)[1]), "=r"((r)[2]), "=r"((r)[3]) : "r"(a))
// fp32-accumulator MMA
#define MMA(c, a, b0v, b1v) \
    asm volatile("mma.sync.aligned.m16n8k16.row.col.f32.f16.f16.f32 " \
        "{%0,%1,%2,%3}, {%4,%5,%6,%7}, {%8,%9}, {%0,%1,%2,%3};" \
        : "+f"((c)[0]), "+f"((c)[1]), "+f"((c)[2]), "+f"((c)[3]) \
        : "r"((a)[0]), "r"((a)[1]), "r"((a)[2]), "r"((a)[3]), "r"(b0v), "r"(b1v))
// fp16-accumulator MMA (QK path)
#define MMAH(c, a, b0v, b1v) \
    asm volatile("mma.sync.aligned.m16n8k16.row.col.f16.f16.f16.f16 " \
        "{%0,%1}, {%2,%3,%4,%5}, {%6,%7}, {%0,%1};" \
        : "+r"((c)[0]), "+r"((c)[1]) \
        : "r"((a)[0]), "r"((a)[1]), "r"((a)[2]), "r"((a)[3]), "r"(b0v), "r"(b1v))
__device__ __forceinline__ void cp16(u32 saddr, const void* g) {
    asm volatile("cp.async.cg.shared.global [%0], [%1], 16;" :: "r"(saddr), "l"(g));
}
#define CP_COMMIT() asm volatile("cp.async.commit_group;")
#define CP_WAIT0()  asm volatile("cp.async.wait_group 0;")
#define CP_WAIT1()  asm volatile("cp.async.wait_group 1;")
__device__ __forceinline__ u32 cvtpack(float lo, float hi) {
    u32 d; asm("cvt.rn.f16x2.f32 %0, %1, %2;" : "=r"(d) : "f"(hi), "f"(lo)); return d;
}
__device__ __forceinline__ u32 ex2h2(u32 x) {
    u32 r; asm("ex2.approx.f16x2 %0, %1;" : "=r"(r) : "r"(x)); return r;
}
__device__ __forceinline__ u32 haddp(u32 a, u32 b) {
    u32 r; asm("add.rn.f16x2 %0, %1, %2;" : "=r"(r) : "r"(a), "r"(b)); return r;
}

// ---------------------------------------------------------------------------
// fp32 -> fp16 convert: x (8192 rows) + Wq/Wk/Wv (768 rows each) in ONE launch
// ---------------------------------------------------------------------------
__global__ __launch_bounds__(192)
void conv_all_kernel(const float* __restrict__ x_f,
                     const float* __restrict__ wq_f, const float* __restrict__ wk_f,
                     const float* __restrict__ wv_f,
                     __half* __restrict__ x_h,
                     __half* __restrict__ wq_h, __half* __restrict__ wk_h,
                     __half* __restrict__ wv_h)
{
    const int bid = blockIdx.x;
    const float* src;
    __half* dst;
    int row;
    if (bid < MM) { src = x_f; dst = x_h; row = bid; }
    else {
        int r = bid - MM;
        int z = r / HH;
        row = r % HH;
        src = (z == 0) ? wq_f : (z == 1) ? wk_f : wv_f;
        dst = (z == 0) ? wq_h : (z == 1) ? wk_h : wv_h;
    }
    const size_t o = (size_t)row * HH + threadIdx.x * 4;
    float4 v = *(const float4*)&src[o];
    *(uint2*)&dst[o] = make_uint2(cvtpack(v.x, v.y), cvtpack(v.z, v.w));
}

// ---------------------------------------------------------------------------
// fp16 tensor-core GEMM + bias + head-layout fp16 epilogue. 2 CTAs/SM.
// ---------------------------------------------------------------------------
#define XRS 144
#define WRS 272
#define GXT (128 * XRS)
#define GWT (64 * WRS)
#define GBUF (GXT + GWT)
#define GSM  (2 * GBUF)

__global__ __launch_bounds__(256, 2)
void gemm_tc_kernel(const __half* __restrict__ Xh,
                    const __half* __restrict__ Wq_h, const __half* __restrict__ Wk_h,
                    const __half* __restrict__ Wv_h,
                    const float* __restrict__ bq, const float* __restrict__ bk,
                    const float* __restrict__ bv,
                    __half* __restrict__ qo, __half* __restrict__ ko,
                    __half* __restrict__ vo)
{
    const int z = blockIdx.z;
    const __half* Wh = (z == 0) ? Wq_h : (z == 1) ? Wk_h : Wv_h;
    const float* bias = (z == 0) ? bq : (z == 1) ? bk : bv;
    __half* gout = (z == 0) ? qo : (z == 1) ? ko : vo;
    const float scale = (z == 0) ? 0.18033688011112042f : 1.0f;

    extern __shared__ char smem[];
    const u32 sb = smem_u32(smem);
    const int tid = threadIdx.x;
    const int w = tid >> 5, lane = tid & 31;
    const int wm = w >> 1, wn = w & 1;
    const int bn = blockIdx.x * 128;
    const int bm = blockIdx.y * 128;

    float acc[2][8][4];
    #pragma unroll
    for (int mi = 0; mi < 2; mi++)
        #pragma unroll
        for (int j = 0; j < 8; j++)
            #pragma unroll
            for (int i = 0; i < 4; i++) acc[mi][j][i] = 0.0f;

    const int frow = (lane & 7) + ((lane >> 3) & 1) * 8;
    const u32 aoff = (u32)(frow * XRS + (lane >> 4) * 16);
    const u32 boff = (u32)(frow * WRS + (lane >> 4) * 16);

    {
        const u32 buf = sb;
        #pragma unroll
        for (int i = 0; i < 4; i++) {
            int c = tid + i * 256;
            int r = c >> 3, o = c & 7;
            cp16(buf + (u32)(r * XRS + o * 16), Xh + (size_t)(bm + r) * HH + o * 8);
        }
        #pragma unroll
        for (int i = 0; i < 4; i++) {
            int c = tid + i * 256;
            int r = c >> 4, o = c & 15;
            cp16(buf + GXT + (u32)(r * WRS + o * 16), Wh + (size_t)r * HH + bn + o * 8);
        }
        CP_COMMIT();
    }

    for (int kc = 0; kc < 12; kc++) {
        if (kc < 11) {
            const u32 buf = sb + ((kc + 1) & 1) * GBUF;
            const int kb = (kc + 1) * 64;
            #pragma unroll
            for (int i = 0; i < 4; i++) {
                int c = tid + i * 256;
                int r = c >> 3, o = c & 7;
                cp16(buf + (u32)(r * XRS + o * 16), Xh + (size_t)(bm + r) * HH + kb + o * 8);
            }
            #pragma unroll
            for (int i = 0; i < 4; i++) {
                int c = tid + i * 256;
                int r = c >> 4, o = c & 15;
                cp16(buf + GXT + (u32)(r * WRS + o * 16), Wh + (size_t)(kb + r) * HH + bn + o * 8);
            }
            CP_COMMIT();
            CP_WAIT1();
        } else {
            CP_WAIT0();
        }
        __syncthreads();

        const u32 XT = sb + (kc & 1) * GBUF;
        const u32 WT = XT + GXT;

        #pragma unroll
        for (int kk = 0; kk < 4; kk++) {
            u32 ah[2][4];
            #pragma unroll
            for (int mi = 0; mi < 2; mi++) {
                u32 a = (u32)((wm * 32 + mi * 16) * XRS) + aoff + kk * 32;
                LDSM4(ah[mi], XT + a);
            }
            #pragma unroll
            for (int nt = 0; nt < 4; nt++) {
                u32 bo = (u32)(kk * 16 * WRS) + boff + (u32)(wn * 128 + nt * 32);
                u32 bh[4];
                LDSM4T(bh, WT + bo);
                #pragma unroll
                for (int mi = 0; mi < 2; mi++) {
                    MMA(acc[mi][2 * nt],     ah[mi], bh[0], bh[1]);
                    MMA(acc[mi][2 * nt + 1], ah[mi], bh[2], bh[3]);
                }
            }
        }
        __syncthreads();
    }

    const int h  = (bn >> 6) + wn;
    const int cl = (lane & 3) * 2;
    const int rl = lane >> 2;
    #pragma unroll
    for (int j = 0; j < 8; j++) {
        const int d = j * 8 + cl;
        const float bx = bias[bn + wn * 64 + d];
        const float by = bias[bn + wn * 64 + d + 1];
        #pragma unroll
        for (int mi = 0; mi < 2; mi++) {
            #pragma unroll
            for (int rr = 0; rr < 2; rr++) {
                const int m = bm + wm * 32 + mi * 16 + rl + rr * 8;
                const int b = m >> 12, s = m & 4095;
                const size_t o = ((size_t)(b * NHH + h) * SS + s) * DHH + d;
                const float y0 = (acc[mi][j][2 * rr]     + bx) * scale;
                const float y1 = (acc[mi][j][2 * rr + 1] + by) * scale;
                *(u32*)&gout[o] = cvtpack(y0, y1);
            }
        }
    }
}

// ---------------------------------------------------------------------------
// mma.sync flash attention v5 (unchanged from R12 best):
// 4 warps x 32 q-rows, 2 CTAs/SM, software-pipelined (j,mi) stages.
// ---------------------------------------------------------------------------
#define RS 144
#define ARR_BYTES (128 * RS)
#define BUF_BYTES (2 * ARR_BYTES)
#define SM_TOTAL  (2 * BUF_BYTES)     // 73728

__global__ __launch_bounds__(128, 2)
void attn_mma_kernel(const __half* __restrict__ qh_g,
                     const __half* __restrict__ kh_g,
                     const __half* __restrict__ vh_g,
                     float* __restrict__ out)
{
    extern __shared__ char smem[];
    const u32 sb = smem_u32(smem);
    const int tid  = threadIdx.x;
    const int w    = tid >> 5;
    const int lane = tid & 31;
    const int qt = blockIdx.x;
    const int bh = blockIdx.y;
    const int b = bh / NHH, h = bh % NHH;

    const size_t bh_base = (size_t)bh * SS * DHH;

    // ---- stage Q (128 rows) into buffer 1, extract 2 A-fragments/warp ----
    {
        const u32 QB = sb + BUF_BYTES;
        const __half* qg = qh_g + bh_base + (size_t)qt * 128 * DHH;
        #pragma unroll
        for (int i = 0; i < 8; i++) {
            int c = tid + i * 128;
            int r = c >> 3, o = c & 7;
            cp16(QB + (u32)(r * RS + o * 16), qg + (size_t)r * DHH + o * 8);
        }
        CP_COMMIT();
        CP_WAIT0();
        __syncthreads();
    }

    const int frow = (lane & 7) + ((lane >> 3) & 1) * 8;
    u32 qf[2][4][4];
    {
        const u32 QB = sb + BUF_BYTES;
        #pragma unroll
        for (int mi = 0; mi < 2; mi++) {
            u32 rbase = (u32)((w * 32 + mi * 16 + frow) * RS + (lane >> 4) * 16);
            #pragma unroll
            for (int k = 0; k < 4; k++)
                LDSM4(qf[mi][k], QB + rbase + k * 32);
        }
    }
    __syncthreads();

    float ctx[2][8][4];
    #pragma unroll
    for (int mi = 0; mi < 2; mi++)
        #pragma unroll
        for (int n = 0; n < 8; n++)
            #pragma unroll
            for (int i = 0; i < 4; i++) ctx[mi][n][i] = 0.0f;
    float ls[2][2] = {{0.f, 0.f}, {0.f, 0.f}};

    const u32 koff = (u32)(((lane >> 4) * 8 + (lane & 7)) * RS + ((lane >> 3) & 1) * 16);
    const u32 voff = (u32)((((lane >> 3) & 1) * 8 + (lane & 7)) * RS + (lane >> 4) * 16);

    // tile 0 -> buffer 0
    {
        #pragma unroll
        for (int i = 0; i < 8; i++) {
            int c = tid + i * 128;
            int r = c >> 3, o = c & 7;
            u32 so = (u32)(r * RS + o * 16);
            cp16(sb + so,             kh_g + bh_base + (size_t)r * DHH + o * 8);
            cp16(sb + ARR_BYTES + so, vh_g + bh_base + (size_t)r * DHH + o * 8);
        }
        CP_COMMIT();
    }

    for (int t = 0; t < 32; ++t) {
        if (t < 31) {
            const u32 nb = sb + ((t + 1) & 1) * BUF_BYTES;
            const size_t gb = bh_base + (size_t)(t + 1) * 128 * DHH;
            #pragma unroll
            for (int i = 0; i < 8; i++) {
                int c = tid + i * 128;
                int r = c >> 3, o = c & 7;
                u32 so = (u32)(r * RS + o * 16);
                cp16(nb + so,             kh_g + gb + (size_t)r * DHH + o * 8);
                cp16(nb + ARR_BYTES + so, vh_g + gb + (size_t)r * DHH + o * 8);
            }
            CP_COMMIT();
            CP_WAIT1();
        } else {
            CP_WAIT0();
        }
        __syncthreads();

        const u32 KH = sb + (t & 1) * BUF_BYTES;
        const u32 VS = KH + ARR_BYTES;

        u32 hls[2][2] = {{0u, 0u}, {0u, 0u}};

        u32 khf[4][4];
        #pragma unroll
        for (int k = 0; k < 4; k++)
            LDSM4(khf[k], KH + koff + k * 32);

        u32 scur[4] = {0u, 0u, 0u, 0u};
        #pragma unroll
        for (int k = 0; k < 4; k++) {
            MMAH(&scur[0], qf[0][k], khf[k][0], khf[k][1]);
            MMAH(&scur[2], qf[0][k], khf[k][2], khf[k][3]);
        }

        u32 vf[4][4];

        #pragma unroll
        for (int st = 0; st < 16; st++) {
            const int j  = st >> 1;
            const int mi = st & 1;

            if (mi == 0) {
                const u32 bj = (u32)(j * 16 * RS);
                #pragma unroll
                for (int tt = 0; tt < 4; tt++)
                    LDSM4T(vf[tt], VS + bj + voff + tt * 32);
            }

            u32 pa[4];
            pa[0] = ex2h2(scur[0]);
            pa[1] = ex2h2(scur[1]);
            pa[2] = ex2h2(scur[2]);
            pa[3] = ex2h2(scur[3]);

            u32 snext[4] = {0u, 0u, 0u, 0u};
            if (st < 15) {
                const int mi2 = (st + 1) & 1;
                if (mi2 == 0) {
                    const int j2 = (st + 1) >> 1;
                    const u32 bj2 = (u32)(j2 * 16 * RS);
                    #pragma unroll
                    for (int k = 0; k < 4; k++)
                        LDSM4(khf[k], KH + bj2 + koff + k * 32);
                }
                #pragma unroll
                for (int k = 0; k < 4; k++) {
                    MMAH(&snext[0], qf[mi2][k], khf[k][0], khf[k][1]);
                    MMAH(&snext[2], qf[mi2][k], khf[k][2], khf[k][3]);
                }
            }

            hls[mi][0] = haddp(hls[mi][0], haddp(pa[0], pa[2]));
            hls[mi][1] = haddp(hls[mi][1], haddp(pa[1], pa[3]));

            #pragma unroll
            for (int tt = 0; tt < 4; tt++) {
                MMA(ctx[mi][2 * tt],     pa, vf[tt][0], vf[tt][1]);
                MMA(ctx[mi][2 * tt + 1], pa, vf[tt][2], vf[tt][3]);
            }

            #pragma unroll
            for (int i = 0; i < 4; i++) scur[i] = snext[i];
        }

        #pragma unroll
        for (int mi = 0; mi < 2; mi++) {
            float2 f0 = __half22float2(*(__half2*)&hls[mi][0]);
            float2 f1 = __half22float2(*(__half2*)&hls[mi][1]);
            ls[mi][0] += f0.x + f0.y;
            ls[mi][1] += f1.x + f1.y;
        }
        __syncthreads();
    }

    #pragma unroll
    for (int mi = 0; mi < 2; mi++) {
        float l0 = ls[mi][0], l1 = ls[mi][1];
        l0 += __shfl_xor_sync(0xffffffffu, l0, 1);
        l0 += __shfl_xor_sync(0xffffffffu, l0, 2);
        l1 += __shfl_xor_sync(0xffffffffu, l1, 1);
        l1 += __shfl_xor_sync(0xffffffffu, l1, 2);
        const float inv0 = 1.0f / l0;
        const float inv1 = 1.0f / l1;

        const int row0 = qt * 128 + w * 32 + mi * 16 + (lane >> 2);
        const int colb = 2 * (lane & 3);
        float* o0 = out + ((size_t)(b * SS) + row0) * HH + h * DHH + colb;
        float* o1 = o0 + 8 * HH;
        #pragma unroll
        for (int n = 0; n < 8; n++) {
            float2 r0, r1;
            r0.x = tanhf(ctx[mi][n][0] * inv0);
            r0.y = tanhf(ctx[mi][n][1] * inv0);
            r1.x = tanhf(ctx[mi][n][2] * inv1);
            r1.y = tanhf(ctx[mi][n][3] * inv1);
            *(float2*)(o0 + 8 * n) = r0;
            *(float2*)(o1 + 8 * n) = r1;
        }
    }
}

// ---------------------------------------------------------------------------
extern "C" void kernel_launch(void* const* d_in, const int* in_sizes, int n_in,
                              void* d_out, int out_size)
{
    const float* x  = (const float*)d_in[0];
    const float* Wq = (const float*)d_in[1];
    const float* bq = (const float*)d_in[2];
    const float* Wk = (const float*)d_in[3];
    const float* bk = (const float*)d_in[4];
    const float* Wv = (const float*)d_in[5];
    const float* bv = (const float*)d_in[6];
    float* out = (float*)d_out;

    __half *xh, *wq, *wk, *wv, *qh, *kh, *vh;
    cudaGetSymbolAddress((void**)&xh, g_xh);
    cudaGetSymbolAddress((void**)&wq, g_wq);
    cudaGetSymbolAddress((void**)&wk, g_wk);
    cudaGetSymbolAddress((void**)&wv, g_wv);
    cudaGetSymbolAddress((void**)&qh, g_qh);
    cudaGetSymbolAddress((void**)&kh, g_kh);
    cudaGetSymbolAddress((void**)&vh, g_vh);

    cudaFuncSetAttribute(gemm_tc_kernel, cudaFuncAttributeMaxDynamicSharedMemorySize, GSM);
    cudaFuncSetAttribute(attn_mma_kernel, cudaFuncAttributeMaxDynamicSharedMemorySize, SM_TOTAL);

    // all fp32->fp16 converts in one launch (x + Wq + Wk + Wv)
    conv_all_kernel<<<MM + 3 * HH, 192>>>(x, Wq, Wk, Wv, xh, wq, wk, wv);

    dim3 ggrid(HH / 128, MM / 128, 3);
    gemm_tc_kernel<<<ggrid, 256, GSM>>>(xh, wq, wk, wv, bq, bk, bv, qh, kh, vh);

    dim3 agrid(SS / 128, NBH);
    attn_mma_kernel<<<agrid, 128, SM_TOTAL>>>(qh, kh, vh, out);
}